// round 16
// baseline (speedup 1.0000x reference)
#include <cuda_runtime.h>
#include <cuda_fp16.h>
#include <math.h>
#include <stdint.h>

#define B_   2
#define S_   2048
#define D_   2048
#define H_   16
#define HKV_ 4
#define HD_  128
#define NT   (B_ * S_)
#define NQKV 3072

// ---------------- scratch ---------------------------------------------------
__device__ __half g_hid[NT * D_];
__device__ __half g_wqkvT[NQKV * D_];
__device__ __half g_woT[(H_*HD_) * D_];
__device__ __half g_at[NT * (H_*HD_)];

__device__ __half g_qh[NT * H_ * HD_];
__device__ __half g_kh[NT * HKV_ * HD_];
__device__ __half g_vth[NT * HKV_ * HD_];
__device__ float4 g_rope[S_ * 32];

// ---------------- helpers ---------------------------------------------------
__device__ __forceinline__ uint32_t s2u(const void* p) {
    return (uint32_t)__cvta_generic_to_shared(p);
}
__device__ __forceinline__ void cpasync16(uint32_t dst, const void* src) {
    asm volatile("cp.async.cg.shared.global [%0], [%1], 16;" :: "r"(dst), "l"(src));
}
#define CP_COMMIT() asm volatile("cp.async.commit_group;")
#define CP_WAIT(N)  asm volatile("cp.async.wait_group %0;" :: "n"(N))

__device__ __forceinline__ void mma_f16(float* d, const uint32_t* a, const uint32_t* b) {
    asm volatile(
        "mma.sync.aligned.m16n8k16.row.col.f32.f16.f16.f32 "
        "{%0,%1,%2,%3}, {%4,%5,%6,%7}, {%8,%9}, {%0,%1,%2,%3};"
        : "+f"(d[0]), "+f"(d[1]), "+f"(d[2]), "+f"(d[3])
        : "r"(a[0]), "r"(a[1]), "r"(a[2]), "r"(a[3]), "r"(b[0]), "r"(b[1]));
}
__device__ __forceinline__ void ldm_x4(uint32_t* r, uint32_t addr) {
    asm volatile("ldmatrix.sync.aligned.m8n8.x4.shared.b16 {%0,%1,%2,%3}, [%4];"
                 : "=r"(r[0]), "=r"(r[1]), "=r"(r[2]), "=r"(r[3]) : "r"(addr));
}
__device__ __forceinline__ uint32_t packh_hi(float x, float y) {
    __half2 h = __floats2half2_rn(x, y);
    return *(uint32_t*)&h;
}

// ---------------- merged prep kernel ----------------------------------------
__global__ __launch_bounds__(256) void prep_kernel(
    const float4* __restrict__ hid, uint2* __restrict__ hid16,
    const float* __restrict__ wq, const float* __restrict__ wk,
    const float* __restrict__ wv, const float* __restrict__ wo,
    __half* __restrict__ wqkvT, __half* __restrict__ woT,
    float4* __restrict__ rope)
{
    const int bid = blockIdx.x;
    const int tid = threadIdx.x;

    if (bid < 8192) {
        int i = bid * 256 + tid;
        float4 v = hid[i];
        __half2 h0 = __floats2half2_rn(v.x, v.y);
        __half2 h1 = __floats2half2_rn(v.z, v.w);
        uint2 H;
        H.x = *(uint32_t*)&h0; H.y = *(uint32_t*)&h1;
        hid16[i] = H;
        return;
    }
    if (bid >= 18432) {
        if (tid >= 32) return;
        int p = bid - 18432, j = tid;
        float i0 = exp2f(-13.287712379549449f * (float)(2 * j)     * (1.0f / 64.0f));
        float i1 = exp2f(-13.287712379549449f * (float)(2 * j + 1) * (1.0f / 64.0f));
        float c0, s0, c1, s1;
        sincosf((float)p * i0, &s0, &c0);
        sincosf((float)p * i1, &s1, &c1);
        rope[p * 32 + j] = make_float4(c0, s0, c1, s1);
        return;
    }

    const float* W; __half* T; int K, N, t;
    if (bid < 12288)      { t = bid - 8192;  W = wq; T = wqkvT;                    K = D_;     N = 2048; }
    else if (bid < 13312) { t = bid - 12288; W = wk; T = wqkvT + (size_t)2048*D_;  K = D_;     N = 512;  }
    else if (bid < 14336) { t = bid - 13312; W = wv; T = wqkvT + (size_t)2560*D_;  K = D_;     N = 512;  }
    else                  { t = bid - 14336; W = wo; T = woT;                      K = H_*HD_; N = D_;   }
    int nb = N / 32;
    int n0 = (t % nb) * 32, k0 = (t / nb) * 32;
    int tx = tid & 31, ty = tid >> 5;

    __shared__ float tbuf[32][33];
    for (int j = ty; j < 32; j += 8)
        tbuf[j][tx] = W[(size_t)(k0 + j) * N + n0 + tx];
    __syncthreads();
    for (int j = ty; j < 32; j += 8)
        T[(size_t)(n0 + j) * K + k0 + tx] = __float2half(tbuf[tx][j]);
}

// ---------------- GEMM tiling: 128x128, 2-stage, 2 CTA/SM -------------------
#define KC      64
#define RSTRIDE 144
#define OFF_B   18432
#define STAGE   36864
#define G_SMEM  (2 * STAGE)     // 73728

// ---------------- QKV GEMM fused with RMSNorm+RoPE+transpose ----------------
__global__ __launch_bounds__(256, 2) void gemm_qkv_fused(
    const __half* __restrict__ A, const __half* __restrict__ B,
    const float* __restrict__ qw, const float* __restrict__ kw,
    const int* __restrict__ pos_ids, const float4* __restrict__ rope,
    __half* __restrict__ Qo, __half* __restrict__ Ko, __half* __restrict__ Vo)
{
    extern __shared__ char sm[];
    const uint32_t smb = s2u(sm);
    const int tid  = threadIdx.x;
    const int wid  = tid >> 5, lane = tid & 31;
    const int wm   = wid & 3, wn = wid >> 2;
    const int g    = lane >> 2, tg = lane & 3;
    const int lm   = lane >> 3, lr = lane & 7;
    const int m0   = blockIdx.y * 128;
    const int bx   = blockIdx.x;
    const int n0   = bx * 128;
    const int K    = D_;

    float acc[2][8][4];
#pragma unroll
    for (int a = 0; a < 2; a++)
#pragma unroll
        for (int b2 = 0; b2 < 8; b2++)
#pragma unroll
            for (int c = 0; c < 4; c++) acc[a][b2][c] = 0.f;

    const int nchunks = K / KC;

    auto load_chunk = [&](int kc, int st) {
        uint32_t base = smb + st * STAGE;
        int k0 = kc * KC;
#pragma unroll
        for (int i = 0; i < 4; i++) {
            int lin = tid + i * 256;
            int r = lin >> 3, sg = lin & 7;
            uint32_t off = r * RSTRIDE + sg * 16;
            cpasync16(base + off,         A + (size_t)(m0 + r) * K + k0 + sg * 8);
            cpasync16(base + OFF_B + off, B + (size_t)(n0 + r) * K + k0 + sg * 8);
        }
        CP_COMMIT();
    };

    auto compute = [&](int st) {
        uint32_t base = smb + st * STAGE;
        uint32_t aaddr = base + (wm * 32 + (lm & 1) * 8 + lr) * RSTRIDE + (lm >> 1) * 16;
        uint32_t baddr = base + OFF_B + (wn * 64 + (lm >> 1) * 8 + lr) * RSTRIDE + (lm & 1) * 16;
#pragma unroll
        for (int ks = 0; ks < 4; ks++) {
            int ko = ks * 32;
            uint32_t ah[2][4];
            ldm_x4(ah[0], aaddr + ko);
            ldm_x4(ah[1], aaddr + 16 * RSTRIDE + ko);
#pragma unroll
            for (int p = 0; p < 4; p++) {
                uint32_t bq[4];
                ldm_x4(bq, baddr + p * 16 * RSTRIDE + ko);
#pragma unroll
                for (int mt = 0; mt < 2; mt++) {
                    mma_f16(acc[mt][2 * p],     ah[mt], bq);
                    mma_f16(acc[mt][2 * p + 1], ah[mt], bq + 2);
                }
            }
        }
    };

    load_chunk(0, 0);
    for (int kc = 0; kc < nchunks; kc++) {
        int st = kc & 1;
        if (kc + 1 < nchunks) load_chunk(kc + 1, st ^ 1);
        if (kc + 1 < nchunks) { CP_WAIT(1); } else { CP_WAIT(0); }
        __syncthreads();
        compute(st);
        __syncthreads();
    }

    // ================= fused epilogue (one head per N-block) =================
    __half* xbuf  = (__half*)sm;            // [128][136] fp16 = 34816 B
    float*  ssbuf = (float*)(sm + 34816);   // [128][2]

    if (bx < 20) {
        const bool isq = bx < 16;
        const float* w = isq ? qw : kw;

#pragma unroll
        for (int mt = 0; mt < 2; mt++) {
            float s0 = 0.f, s1 = 0.f;
#pragma unroll
            for (int nt = 0; nt < 8; nt++) {
                s0 += acc[mt][nt][0] * acc[mt][nt][0] + acc[mt][nt][1] * acc[mt][nt][1];
                s1 += acc[mt][nt][2] * acc[mt][nt][2] + acc[mt][nt][3] * acc[mt][nt][3];
            }
            s0 += __shfl_xor_sync(0xffffffffu, s0, 1);
            s0 += __shfl_xor_sync(0xffffffffu, s0, 2);
            s1 += __shfl_xor_sync(0xffffffffu, s1, 1);
            s1 += __shfl_xor_sync(0xffffffffu, s1, 2);
            if (tg == 0) {
                int R = wm * 32 + mt * 16 + g;
                ssbuf[R * 2 + wn]       = s0;
                ssbuf[(R + 8) * 2 + wn] = s1;
            }
        }
        __syncthreads();

#pragma unroll
        for (int mt = 0; mt < 2; mt++) {
            int R0 = wm * 32 + mt * 16 + g, R1 = R0 + 8;
            float r0 = rsqrtf((ssbuf[R0 * 2] + ssbuf[R0 * 2 + 1]) * (1.0f / 128.0f) + 1e-6f);
            float r1 = rsqrtf((ssbuf[R1 * 2] + ssbuf[R1 * 2 + 1]) * (1.0f / 128.0f) + 1e-6f);
#pragma unroll
            for (int nt = 0; nt < 8; nt++) {
                int c = wn * 64 + nt * 8 + tg * 2;
                float w0 = w[c], w1 = w[c + 1];
                acc[mt][nt][0] *= r0 * w0; acc[mt][nt][1] *= r0 * w1;
                acc[mt][nt][2] *= r1 * w0; acc[mt][nt][3] *= r1 * w1;
                *(uint32_t*)(xbuf + R0 * 136 + c) = packh_hi(acc[mt][nt][0], acc[mt][nt][1]);
                *(uint32_t*)(xbuf + R1 * 136 + c) = packh_hi(acc[mt][nt][2], acc[mt][nt][3]);
            }
        }
        __syncthreads();

        __half* dst = isq ? Qo : Ko;
        const int nheads = isq ? H_ : HKV_;
        const int head = isq ? bx : bx - 16;
#pragma unroll
        for (int mt = 0; mt < 2; mt++) {
#pragma unroll
            for (int hf = 0; hf < 2; hf++) {
                int R = wm * 32 + mt * 16 + g + hf * 8;
                int tok = blockIdx.y * 128 + R;
                int b = tok >> 11, s = tok & 2047;
                int p = pos_ids[tok];
#pragma unroll
                for (int nt = 0; nt < 8; nt++) {
                    int d = wn * 64 + nt * 8 + tg * 2;
                    float4 cs = rope[p * 32 + ((d & 63) >> 1)];
                    uint32_t pv = *(uint32_t*)(xbuf + R * 136 + (d ^ 64));
                    __half2 ph2 = *(__half2*)&pv;
                    float rt0 = __half2float(ph2.x), rt1 = __half2float(ph2.y);
                    if (d < 64) { rt0 = -rt0; rt1 = -rt1; }
                    float x0 = acc[mt][nt][hf * 2 + 0], x1 = acc[mt][nt][hf * 2 + 1];
                    float o0 = x0 * cs.x + rt0 * cs.y;
                    float o1 = x1 * cs.z + rt1 * cs.w;
                    size_t off = (((size_t)b * nheads + head) * S_ + s) * HD_ + d;
                    *(uint32_t*)(dst + off) = packh_hi(o0, o1);
                }
            }
        }
    } else {
        const int kvh = bx - 20;
#pragma unroll
        for (int mt = 0; mt < 2; mt++) {
#pragma unroll
            for (int hf = 0; hf < 2; hf++) {
                int R = wm * 32 + mt * 16 + g + hf * 8;
                int tok = blockIdx.y * 128 + R;
                int b = tok >> 11, s = tok & 2047;
#pragma unroll
                for (int nt = 0; nt < 8; nt++) {
                    int d = wn * 64 + nt * 8 + tg * 2;
                    size_t off = (((size_t)b * HKV_ + kvh) * HD_ + d) * S_ + s;
                    Vo[off]      = __float2half(acc[mt][nt][hf * 2 + 0]);
                    Vo[off + S_] = __float2half(acc[mt][nt][hf * 2 + 1]);
                }
            }
        }
    }
}

// ---------------- generic fp16 GEMM (WO), 128x128, 2 CTA/SM -----------------
__global__ __launch_bounds__(256, 2) void gemm_mma(
    const __half* __restrict__ A, const __half* __restrict__ B,
    float* __restrict__ C, int M, int N, int K)
{
    extern __shared__ char sm[];
    const uint32_t smb = s2u(sm);
    const int tid  = threadIdx.x;
    const int wid  = tid >> 5, lane = tid & 31;
    const int wm   = wid & 3, wn = wid >> 2;
    const int g    = lane >> 2, tg = lane & 3;
    const int lm   = lane >> 3, lr = lane & 7;
    const int m0   = blockIdx.y * 128, n0 = blockIdx.x * 128;

    float acc[2][8][4];
#pragma unroll
    for (int a = 0; a < 2; a++)
#pragma unroll
        for (int b = 0; b < 8; b++)
#pragma unroll
            for (int c = 0; c < 4; c++) acc[a][b][c] = 0.f;

    const int nchunks = K / KC;

    auto load_chunk = [&](int kc, int st) {
        uint32_t base = smb + st * STAGE;
        int k0 = kc * KC;
#pragma unroll
        for (int i = 0; i < 4; i++) {
            int lin = tid + i * 256;
            int r = lin >> 3, sg = lin & 7;
            uint32_t off = r * RSTRIDE + sg * 16;
            cpasync16(base + off,         A + (size_t)(m0 + r) * K + k0 + sg * 8);
            cpasync16(base + OFF_B + off, B + (size_t)(n0 + r) * K + k0 + sg * 8);
        }
        CP_COMMIT();
    };

    auto compute = [&](int st) {
        uint32_t base = smb + st * STAGE;
        uint32_t aaddr = base + (wm * 32 + (lm & 1) * 8 + lr) * RSTRIDE + (lm >> 1) * 16;
        uint32_t baddr = base + OFF_B + (wn * 64 + (lm >> 1) * 8 + lr) * RSTRIDE + (lm & 1) * 16;
#pragma unroll
        for (int ks = 0; ks < 4; ks++) {
            int ko = ks * 32;
            uint32_t ah[2][4];
            ldm_x4(ah[0], aaddr + ko);
            ldm_x4(ah[1], aaddr + 16 * RSTRIDE + ko);
#pragma unroll
            for (int p = 0; p < 4; p++) {
                uint32_t bq[4];
                ldm_x4(bq, baddr + p * 16 * RSTRIDE + ko);
#pragma unroll
                for (int mt = 0; mt < 2; mt++) {
                    mma_f16(acc[mt][2 * p],     ah[mt], bq);
                    mma_f16(acc[mt][2 * p + 1], ah[mt], bq + 2);
                }
            }
        }
    };

    load_chunk(0, 0);
    for (int kc = 0; kc < nchunks; kc++) {
        int st = kc & 1;
        if (kc + 1 < nchunks) load_chunk(kc + 1, st ^ 1);
        if (kc + 1 < nchunks) { CP_WAIT(1); } else { CP_WAIT(0); }
        __syncthreads();
        compute(st);
        __syncthreads();
    }

#pragma unroll
    for (int mt = 0; mt < 2; mt++)
#pragma unroll
        for (int nt = 0; nt < 8; nt++) {
            int r = m0 + wm * 32 + mt * 16 + g;
            int c = n0 + wn * 64 + nt * 8 + tg * 2;
            float2 v0 = make_float2(acc[mt][nt][0], acc[mt][nt][1]);
            float2 v1 = make_float2(acc[mt][nt][2], acc[mt][nt][3]);
            *(float2*)&C[(size_t)r * N + c]       = v0;
            *(float2*)&C[(size_t)(r + 8) * N + c] = v1;
        }
}

// ---------------- mma.sync fp16 causal flash attention, 1 CTA/SM ------------
#define FQSTR 272
#define FKSTR 272
#define FVSTR 144
#define QBYTES (128 * FQSTR)
#define KSTAGE (64 * FKSTR)
#define VSTAGE (128 * FVSTR)
#define OFF_Q  0
#define OFF_K  QBYTES
#define OFF_V  (OFF_K + 2 * KSTAGE)
#define FLASH_SMEM (OFF_V + 2 * VSTAGE)      // 106496

__global__ __launch_bounds__(256, 1) void flash_mma(
    const __half* __restrict__ Qh, const __half* __restrict__ Kh,
    const __half* __restrict__ Vth, __half* __restrict__ Oh)
{
    extern __shared__ char sm[];
    const uint32_t smb = s2u(sm);
    const int tid = threadIdx.x, wid = tid >> 5, lane = tid & 31;
    const int g = lane >> 2, tg = lane & 3;
    const int lm = lane >> 3, lr = lane & 7;
    const int qb = gridDim.x - 1 - blockIdx.x;
    const int bh = blockIdx.y;
    const int b = bh / H_, h = bh % H_;
    const int kvh = h / (H_ / HKV_);
    const int q0 = qb * 128;
    const int nkb = 2 * qb + 2;

    const __half* Qhg = Qh + (((size_t)b * H_ + h) * S_ + q0) * HD_;
    const __half* Khg = Kh + ((size_t)b * HKV_ + kvh) * S_ * HD_;
    const __half* Vhg = Vth + ((size_t)b * HKV_ + kvh) * (size_t)HD_ * S_;

    for (int i = tid; i < 2048; i += 256) {
        int r = i >> 4, c = i & 15;
        cpasync16(smb + OFF_Q + r * FQSTR + c * 16, Qhg + (size_t)r * HD_ + c * 8);
    }
    CP_COMMIT();

    auto load_kv = [&](int kb, int st) {
        uint32_t kbase = smb + OFF_K + st * KSTAGE;
        const __half* kh = Khg + (size_t)kb * 64 * HD_;
        for (int i = tid; i < 1024; i += 256) {
            int r = i >> 4, c = i & 15;
            cpasync16(kbase + r * FKSTR + c * 16, kh + (size_t)r * HD_ + c * 8);
        }
        uint32_t vbase = smb + OFF_V + st * VSTAGE;
        const __half* vh = Vhg + kb * 64;
        for (int i = tid; i < 1024; i += 256) {
            int r = i >> 3, c = i & 7;
            cpasync16(vbase + r * FVSTR + c * 16, vh + (size_t)r * S_ + c * 8);
        }
        CP_COMMIT();
    };

    load_kv(0, 0);
    if (nkb > 1) load_kv(1, 1);

    float m0 = -1e30f, m1 = -1e30f, l0 = 0.f, l1 = 0.f;
    float acc[16][4];
#pragma unroll
    for (int i = 0; i < 16; i++)
#pragma unroll
        for (int j = 0; j < 4; j++) acc[i][j] = 0.f;

    const int qi0 = q0 + wid * 16 + g;
    const int qi1 = qi0 + 8;
    const int qimax = q0 + wid * 16 + 15;
    const float sc = 0.08838834764831845f;

    const uint32_t aaddr = smb + OFF_Q + (wid * 16 + (lm & 1) * 8 + lr) * FQSTR + (lm >> 1) * 16;
    const uint32_t brow_off = ((lm >> 1) * 8 + lr);
    const uint32_t bcol_off = (lm & 1) * 16;

    for (int kb = 0; kb < nkb; kb++) {
        int st = kb & 1;
        if (kb + 1 < nkb) { CP_WAIT(1); } else { CP_WAIT(0); }
        __syncthreads();

        if (kb * 64 <= qimax) {
            float c[8][4];
#pragma unroll
            for (int i = 0; i < 8; i++)
#pragma unroll
                for (int j = 0; j < 4; j++) c[i][j] = 0.f;

            uint32_t kaddr = smb + OFF_K + st * KSTAGE + brow_off * FKSTR + bcol_off;
#pragma unroll
            for (int ks = 0; ks < 8; ks++) {
                int ko = ks * 32;
                uint32_t ah[4];
                ldm_x4(ah, aaddr + ko);
#pragma unroll
                for (int p = 0; p < 4; p++) {
                    if (kb * 64 + p * 16 <= qimax) {   // causal p-tile skip (exact)
                        uint32_t bq[4];
                        ldm_x4(bq, kaddr + p * 16 * FKSTR + ko);
                        mma_f16(c[2 * p],     ah, bq);
                        mma_f16(c[2 * p + 1], ah, bq + 2);
                    }
                }
            }

#pragma unroll
            for (int nt = 0; nt < 8; nt++) {
                int k0c = kb * 64 + nt * 8 + tg * 2;
                c[nt][0] = (k0c     <= qi0) ? c[nt][0] * sc : -1e30f;
                c[nt][1] = (k0c + 1 <= qi0) ? c[nt][1] * sc : -1e30f;
                c[nt][2] = (k0c     <= qi1) ? c[nt][2] * sc : -1e30f;
                c[nt][3] = (k0c + 1 <= qi1) ? c[nt][3] * sc : -1e30f;
            }

            float rm0 = -1e30f, rm1 = -1e30f;
#pragma unroll
            for (int nt = 0; nt < 8; nt++) {
                rm0 = fmaxf(rm0, fmaxf(c[nt][0], c[nt][1]));
                rm1 = fmaxf(rm1, fmaxf(c[nt][2], c[nt][3]));
            }
            rm0 = fmaxf(rm0, __shfl_xor_sync(0xffffffffu, rm0, 1));
            rm0 = fmaxf(rm0, __shfl_xor_sync(0xffffffffu, rm0, 2));
            rm1 = fmaxf(rm1, __shfl_xor_sync(0xffffffffu, rm1, 1));
            rm1 = fmaxf(rm1, __shfl_xor_sync(0xffffffffu, rm1, 2));
            float mn0 = fmaxf(m0, rm0), mn1 = fmaxf(m1, rm1);
            float cr0 = __expf(m0 - mn0), cr1 = __expf(m1 - mn1);
            m0 = mn0; m1 = mn1;
            float rs0 = 0.f, rs1 = 0.f;
#pragma unroll
            for (int nt = 0; nt < 8; nt++) {
                c[nt][0] = __expf(c[nt][0] - mn0);
                c[nt][1] = __expf(c[nt][1] - mn0);
                c[nt][2] = __expf(c[nt][2] - mn1);
                c[nt][3] = __expf(c[nt][3] - mn1);
                rs0 += c[nt][0] + c[nt][1];
                rs1 += c[nt][2] + c[nt][3];
            }
            rs0 += __shfl_xor_sync(0xffffffffu, rs0, 1);
            rs0 += __shfl_xor_sync(0xffffffffu, rs0, 2);
            rs1 += __shfl_xor_sync(0xffffffffu, rs1, 1);
            rs1 += __shfl_xor_sync(0xffffffffu, rs1, 2);
            l0 = l0 * cr0 + rs0;
            l1 = l1 * cr1 + rs1;
#pragma unroll
            for (int nt = 0; nt < 16; nt++) {
                acc[nt][0] *= cr0; acc[nt][1] *= cr0;
                acc[nt][2] *= cr1; acc[nt][3] *= cr1;
            }

            uint32_t ph[4][4];
#pragma unroll
            for (int s = 0; s < 4; s++) {
                ph[s][0] = packh_hi(c[2*s][0],   c[2*s][1]);
                ph[s][1] = packh_hi(c[2*s][2],   c[2*s][3]);
                ph[s][2] = packh_hi(c[2*s+1][0], c[2*s+1][1]);
                ph[s][3] = packh_hi(c[2*s+1][2], c[2*s+1][3]);
            }

            uint32_t vaddr = smb + OFF_V + st * VSTAGE + brow_off * FVSTR + bcol_off;
#pragma unroll
            for (int s = 0; s < 4; s++) {
#pragma unroll
                for (int p = 0; p < 8; p++) {
                    uint32_t bq[4];
                    ldm_x4(bq, vaddr + p * 16 * FVSTR + s * 32);
                    mma_f16(acc[2 * p],     ph[s], bq);
                    mma_f16(acc[2 * p + 1], ph[s], bq + 2);
                }
            }
        }

        __syncthreads();
        if (kb + 2 < nkb) load_kv(kb + 2, st);
    }

    float rl0 = 1.f / l0, rl1 = 1.f / l1;
    int t0 = b * S_ + q0 + wid * 16 + g;
    size_t o0 = (size_t)t0 * (H_ * HD_) + h * HD_;
    size_t o1 = (size_t)(t0 + 8) * (H_ * HD_) + h * HD_;
#pragma unroll
    for (int nt = 0; nt < 16; nt++) {
        int d = nt * 8 + tg * 2;
        *(uint32_t*)(Oh + o0 + d) = packh_hi(acc[nt][0] * rl0, acc[nt][1] * rl0);
        *(uint32_t*)(Oh + o1 + d) = packh_hi(acc[nt][2] * rl1, acc[nt][3] * rl1);
    }
}

// ---------------------------------------------------------------------------
extern "C" void kernel_launch(void* const* d_in, const int* in_sizes, int n_in,
                              void* d_out, int out_size)
{
    const float* hidden = (const float*)d_in[0];
    const float* wq     = (const float*)d_in[1];
    const float* wk     = (const float*)d_in[2];
    const float* wv     = (const float*)d_in[3];
    const float* wo     = (const float*)d_in[4];
    const float* qw     = (const float*)d_in[5];
    const float* kw     = (const float*)d_in[6];
    const int*   pos    = (const int*)d_in[7];
    float* out = (float*)d_out;

    __half *hid16, *wqkvT, *woT, *at16, *qh, *kh, *vth;
    float4* rope;
    cudaGetSymbolAddress((void**)&hid16, g_hid);
    cudaGetSymbolAddress((void**)&wqkvT, g_wqkvT);
    cudaGetSymbolAddress((void**)&woT,   g_woT);
    cudaGetSymbolAddress((void**)&at16,  g_at);
    cudaGetSymbolAddress((void**)&qh,    g_qh);
    cudaGetSymbolAddress((void**)&kh,    g_kh);
    cudaGetSymbolAddress((void**)&vth,   g_vth);
    cudaGetSymbolAddress((void**)&rope,  g_rope);

    cudaFuncSetAttribute(gemm_qkv_fused, cudaFuncAttributeMaxDynamicSharedMemorySize,
                         (int)G_SMEM);
    cudaFuncSetAttribute(gemm_mma, cudaFuncAttributeMaxDynamicSharedMemorySize,
                         (int)G_SMEM);
    cudaFuncSetAttribute(flash_mma, cudaFuncAttributeMaxDynamicSharedMemorySize,
                         (int)FLASH_SMEM);

    // one prep launch: convert + 4 weight transposes + rope table
    prep_kernel<<<20480, 256>>>((const float4*)hidden, (uint2*)hid16,
                                wq, wk, wv, wo, wqkvT, woT, rope);

    // fused QKV projection + RMSNorm + RoPE + head transpose
    gemm_qkv_fused<<<dim3(NQKV/128, NT/128), 256, G_SMEM>>>(
        hid16, wqkvT, qw, kw, pos, rope, qh, kh, vth);

    // tensor-core causal flash attention (fp16) -> attn fp16
    flash_mma<<<dim3(S_/128, B_*H_), 256, FLASH_SMEM>>>(qh, kh, vth, at16);

    // output projection (fp16)
    gemm_mma<<<dim3(D_/128, NT/128), 256, G_SMEM>>>(at16, woT, out, NT, D_, D_);
}

// round 17
// speedup vs baseline: 1.0548x; 1.0548x over previous
#include <cuda_runtime.h>
#include <cuda_fp16.h>
#include <math.h>
#include <stdint.h>

#define B_   2
#define S_   2048
#define D_   2048
#define H_   16
#define HKV_ 4
#define HD_  128
#define NT   (B_ * S_)
#define NQKV 3072

// ---------------- scratch ---------------------------------------------------
__device__ __half g_hid[NT * D_];
__device__ __half g_wqkvT[NQKV * D_];
__device__ __half g_woT[(H_*HD_) * D_];
__device__ __half g_at[NT * (H_*HD_)];

__device__ __half g_qh[NT * H_ * HD_];
__device__ __half g_kh[NT * HKV_ * HD_];
__device__ __half g_vth[NT * HKV_ * HD_];
__device__ float4 g_rope[S_ * 32];

// ---------------- helpers ---------------------------------------------------
__device__ __forceinline__ uint32_t s2u(const void* p) {
    return (uint32_t)__cvta_generic_to_shared(p);
}
__device__ __forceinline__ void cpasync16(uint32_t dst, const void* src) {
    asm volatile("cp.async.cg.shared.global [%0], [%1], 16;" :: "r"(dst), "l"(src));
}
#define CP_COMMIT() asm volatile("cp.async.commit_group;")
#define CP_WAIT(N)  asm volatile("cp.async.wait_group %0;" :: "n"(N))

__device__ __forceinline__ void mma_f16(float* d, const uint32_t* a, const uint32_t* b) {
    asm volatile(
        "mma.sync.aligned.m16n8k16.row.col.f32.f16.f16.f32 "
        "{%0,%1,%2,%3}, {%4,%5,%6,%7}, {%8,%9}, {%0,%1,%2,%3};"
        : "+f"(d[0]), "+f"(d[1]), "+f"(d[2]), "+f"(d[3])
        : "r"(a[0]), "r"(a[1]), "r"(a[2]), "r"(a[3]), "r"(b[0]), "r"(b[1]));
}
__device__ __forceinline__ void ldm_x4(uint32_t* r, uint32_t addr) {
    asm volatile("ldmatrix.sync.aligned.m8n8.x4.shared.b16 {%0,%1,%2,%3}, [%4];"
                 : "=r"(r[0]), "=r"(r[1]), "=r"(r[2]), "=r"(r[3]) : "r"(addr));
}
__device__ __forceinline__ uint32_t packh_hi(float x, float y) {
    __half2 h = __floats2half2_rn(x, y);
    return *(uint32_t*)&h;
}

// ---------------- merged prep kernel ----------------------------------------
__global__ __launch_bounds__(256) void prep_kernel(
    const float4* __restrict__ hid, uint2* __restrict__ hid16,
    const float* __restrict__ wq, const float* __restrict__ wk,
    const float* __restrict__ wv, const float* __restrict__ wo,
    __half* __restrict__ wqkvT, __half* __restrict__ woT,
    float4* __restrict__ rope)
{
    const int bid = blockIdx.x;
    const int tid = threadIdx.x;

    if (bid < 8192) {
        int i = bid * 256 + tid;
        float4 v = hid[i];
        __half2 h0 = __floats2half2_rn(v.x, v.y);
        __half2 h1 = __floats2half2_rn(v.z, v.w);
        uint2 H;
        H.x = *(uint32_t*)&h0; H.y = *(uint32_t*)&h1;
        hid16[i] = H;
        return;
    }
    if (bid >= 18432) {
        if (tid >= 32) return;
        int p = bid - 18432, j = tid;
        float i0 = exp2f(-13.287712379549449f * (float)(2 * j)     * (1.0f / 64.0f));
        float i1 = exp2f(-13.287712379549449f * (float)(2 * j + 1) * (1.0f / 64.0f));
        float c0, s0, c1, s1;
        sincosf((float)p * i0, &s0, &c0);
        sincosf((float)p * i1, &s1, &c1);
        rope[p * 32 + j] = make_float4(c0, s0, c1, s1);
        return;
    }

    const float* W; __half* T; int K, N, t;
    if (bid < 12288)      { t = bid - 8192;  W = wq; T = wqkvT;                    K = D_;     N = 2048; }
    else if (bid < 13312) { t = bid - 12288; W = wk; T = wqkvT + (size_t)2048*D_;  K = D_;     N = 512;  }
    else if (bid < 14336) { t = bid - 13312; W = wv; T = wqkvT + (size_t)2560*D_;  K = D_;     N = 512;  }
    else                  { t = bid - 14336; W = wo; T = woT;                      K = H_*HD_; N = D_;   }
    int nb = N / 32;
    int n0 = (t % nb) * 32, k0 = (t / nb) * 32;
    int tx = tid & 31, ty = tid >> 5;

    __shared__ float tbuf[32][33];
    for (int j = ty; j < 32; j += 8)
        tbuf[j][tx] = W[(size_t)(k0 + j) * N + n0 + tx];
    __syncthreads();
    for (int j = ty; j < 32; j += 8)
        T[(size_t)(n0 + j) * K + k0 + tx] = __float2half(tbuf[tx][j]);
}

// ---------------- GEMM tiling: 128x128, 2-stage, 2 CTA/SM -------------------
#define KC      64
#define RSTRIDE 144
#define OFF_B   18432
#define STAGE   36864
#define G_SMEM  (2 * STAGE)     // 73728

// ---------------- QKV GEMM fused with RMSNorm+RoPE+transpose ----------------
__global__ __launch_bounds__(256, 2) void gemm_qkv_fused(
    const __half* __restrict__ A, const __half* __restrict__ B,
    const float* __restrict__ qw, const float* __restrict__ kw,
    const int* __restrict__ pos_ids, const float4* __restrict__ rope,
    __half* __restrict__ Qo, __half* __restrict__ Ko, __half* __restrict__ Vo)
{
    extern __shared__ char sm[];
    const uint32_t smb = s2u(sm);
    const int tid  = threadIdx.x;
    const int wid  = tid >> 5, lane = tid & 31;
    const int wm   = wid & 3, wn = wid >> 2;
    const int g    = lane >> 2, tg = lane & 3;
    const int lm   = lane >> 3, lr = lane & 7;
    const int m0   = blockIdx.y * 128;
    const int bx   = blockIdx.x;
    const int n0   = bx * 128;
    const int K    = D_;

    float acc[2][8][4];
#pragma unroll
    for (int a = 0; a < 2; a++)
#pragma unroll
        for (int b2 = 0; b2 < 8; b2++)
#pragma unroll
            for (int c = 0; c < 4; c++) acc[a][b2][c] = 0.f;

    const int nchunks = K / KC;

    auto load_chunk = [&](int kc, int st) {
        uint32_t base = smb + st * STAGE;
        int k0 = kc * KC;
#pragma unroll
        for (int i = 0; i < 4; i++) {
            int lin = tid + i * 256;
            int r = lin >> 3, sg = lin & 7;
            uint32_t off = r * RSTRIDE + sg * 16;
            cpasync16(base + off,         A + (size_t)(m0 + r) * K + k0 + sg * 8);
            cpasync16(base + OFF_B + off, B + (size_t)(n0 + r) * K + k0 + sg * 8);
        }
        CP_COMMIT();
    };

    auto compute = [&](int st) {
        uint32_t base = smb + st * STAGE;
        uint32_t aaddr = base + (wm * 32 + (lm & 1) * 8 + lr) * RSTRIDE + (lm >> 1) * 16;
        uint32_t baddr = base + OFF_B + (wn * 64 + (lm >> 1) * 8 + lr) * RSTRIDE + (lm & 1) * 16;
#pragma unroll
        for (int ks = 0; ks < 4; ks++) {
            int ko = ks * 32;
            uint32_t ah[2][4];
            ldm_x4(ah[0], aaddr + ko);
            ldm_x4(ah[1], aaddr + 16 * RSTRIDE + ko);
#pragma unroll
            for (int p = 0; p < 4; p++) {
                uint32_t bq[4];
                ldm_x4(bq, baddr + p * 16 * RSTRIDE + ko);
#pragma unroll
                for (int mt = 0; mt < 2; mt++) {
                    mma_f16(acc[mt][2 * p],     ah[mt], bq);
                    mma_f16(acc[mt][2 * p + 1], ah[mt], bq + 2);
                }
            }
        }
    };

    load_chunk(0, 0);
    for (int kc = 0; kc < nchunks; kc++) {
        int st = kc & 1;
        if (kc + 1 < nchunks) load_chunk(kc + 1, st ^ 1);
        if (kc + 1 < nchunks) { CP_WAIT(1); } else { CP_WAIT(0); }
        __syncthreads();
        compute(st);
        __syncthreads();
    }

    // ================= fused epilogue (one head per N-block) =================
    __half* xbuf  = (__half*)sm;            // [128][136] fp16 = 34816 B
    float*  ssbuf = (float*)(sm + 34816);   // [128][2]

    if (bx < 20) {
        const bool isq = bx < 16;
        const float* w = isq ? qw : kw;

#pragma unroll
        for (int mt = 0; mt < 2; mt++) {
            float s0 = 0.f, s1 = 0.f;
#pragma unroll
            for (int nt = 0; nt < 8; nt++) {
                s0 += acc[mt][nt][0] * acc[mt][nt][0] + acc[mt][nt][1] * acc[mt][nt][1];
                s1 += acc[mt][nt][2] * acc[mt][nt][2] + acc[mt][nt][3] * acc[mt][nt][3];
            }
            s0 += __shfl_xor_sync(0xffffffffu, s0, 1);
            s0 += __shfl_xor_sync(0xffffffffu, s0, 2);
            s1 += __shfl_xor_sync(0xffffffffu, s1, 1);
            s1 += __shfl_xor_sync(0xffffffffu, s1, 2);
            if (tg == 0) {
                int R = wm * 32 + mt * 16 + g;
                ssbuf[R * 2 + wn]       = s0;
                ssbuf[(R + 8) * 2 + wn] = s1;
            }
        }
        __syncthreads();

#pragma unroll
        for (int mt = 0; mt < 2; mt++) {
            int R0 = wm * 32 + mt * 16 + g, R1 = R0 + 8;
            float r0 = rsqrtf((ssbuf[R0 * 2] + ssbuf[R0 * 2 + 1]) * (1.0f / 128.0f) + 1e-6f);
            float r1 = rsqrtf((ssbuf[R1 * 2] + ssbuf[R1 * 2 + 1]) * (1.0f / 128.0f) + 1e-6f);
#pragma unroll
            for (int nt = 0; nt < 8; nt++) {
                int c = wn * 64 + nt * 8 + tg * 2;
                float w0 = w[c], w1 = w[c + 1];
                acc[mt][nt][0] *= r0 * w0; acc[mt][nt][1] *= r0 * w1;
                acc[mt][nt][2] *= r1 * w0; acc[mt][nt][3] *= r1 * w1;
                *(uint32_t*)(xbuf + R0 * 136 + c) = packh_hi(acc[mt][nt][0], acc[mt][nt][1]);
                *(uint32_t*)(xbuf + R1 * 136 + c) = packh_hi(acc[mt][nt][2], acc[mt][nt][3]);
            }
        }
        __syncthreads();

        __half* dst = isq ? Qo : Ko;
        const int nheads = isq ? H_ : HKV_;
        const int head = isq ? bx : bx - 16;
#pragma unroll
        for (int mt = 0; mt < 2; mt++) {
#pragma unroll
            for (int hf = 0; hf < 2; hf++) {
                int R = wm * 32 + mt * 16 + g + hf * 8;
                int tok = blockIdx.y * 128 + R;
                int b = tok >> 11, s = tok & 2047;
                int p = pos_ids[tok];
#pragma unroll
                for (int nt = 0; nt < 8; nt++) {
                    int d = wn * 64 + nt * 8 + tg * 2;
                    float4 cs = rope[p * 32 + ((d & 63) >> 1)];
                    uint32_t pv = *(uint32_t*)(xbuf + R * 136 + (d ^ 64));
                    __half2 ph2 = *(__half2*)&pv;
                    float rt0 = __half2float(ph2.x), rt1 = __half2float(ph2.y);
                    if (d < 64) { rt0 = -rt0; rt1 = -rt1; }
                    float x0 = acc[mt][nt][hf * 2 + 0], x1 = acc[mt][nt][hf * 2 + 1];
                    float o0 = x0 * cs.x + rt0 * cs.y;
                    float o1 = x1 * cs.z + rt1 * cs.w;
                    size_t off = (((size_t)b * nheads + head) * S_ + s) * HD_ + d;
                    *(uint32_t*)(dst + off) = packh_hi(o0, o1);
                }
            }
        }
    } else {
        const int kvh = bx - 20;
#pragma unroll
        for (int mt = 0; mt < 2; mt++) {
#pragma unroll
            for (int hf = 0; hf < 2; hf++) {
                int R = wm * 32 + mt * 16 + g + hf * 8;
                int tok = blockIdx.y * 128 + R;
                int b = tok >> 11, s = tok & 2047;
#pragma unroll
                for (int nt = 0; nt < 8; nt++) {
                    int d = wn * 64 + nt * 8 + tg * 2;
                    size_t off = (((size_t)b * HKV_ + kvh) * HD_ + d) * S_ + s;
                    Vo[off]      = __float2half(acc[mt][nt][hf * 2 + 0]);
                    Vo[off + S_] = __float2half(acc[mt][nt][hf * 2 + 1]);
                }
            }
        }
    }
}

// ---------------- generic fp16 GEMM (WO), 128x128, 2 CTA/SM -----------------
__global__ __launch_bounds__(256, 2) void gemm_mma(
    const __half* __restrict__ A, const __half* __restrict__ B,
    float* __restrict__ C, int M, int N, int K)
{
    extern __shared__ char sm[];
    const uint32_t smb = s2u(sm);
    const int tid  = threadIdx.x;
    const int wid  = tid >> 5, lane = tid & 31;
    const int wm   = wid & 3, wn = wid >> 2;
    const int g    = lane >> 2, tg = lane & 3;
    const int lm   = lane >> 3, lr = lane & 7;
    const int m0   = blockIdx.y * 128, n0 = blockIdx.x * 128;

    float acc[2][8][4];
#pragma unroll
    for (int a = 0; a < 2; a++)
#pragma unroll
        for (int b = 0; b < 8; b++)
#pragma unroll
            for (int c = 0; c < 4; c++) acc[a][b][c] = 0.f;

    const int nchunks = K / KC;

    auto load_chunk = [&](int kc, int st) {
        uint32_t base = smb + st * STAGE;
        int k0 = kc * KC;
#pragma unroll
        for (int i = 0; i < 4; i++) {
            int lin = tid + i * 256;
            int r = lin >> 3, sg = lin & 7;
            uint32_t off = r * RSTRIDE + sg * 16;
            cpasync16(base + off,         A + (size_t)(m0 + r) * K + k0 + sg * 8);
            cpasync16(base + OFF_B + off, B + (size_t)(n0 + r) * K + k0 + sg * 8);
        }
        CP_COMMIT();
    };

    auto compute = [&](int st) {
        uint32_t base = smb + st * STAGE;
        uint32_t aaddr = base + (wm * 32 + (lm & 1) * 8 + lr) * RSTRIDE + (lm >> 1) * 16;
        uint32_t baddr = base + OFF_B + (wn * 64 + (lm >> 1) * 8 + lr) * RSTRIDE + (lm & 1) * 16;
#pragma unroll
        for (int ks = 0; ks < 4; ks++) {
            int ko = ks * 32;
            uint32_t ah[2][4];
            ldm_x4(ah[0], aaddr + ko);
            ldm_x4(ah[1], aaddr + 16 * RSTRIDE + ko);
#pragma unroll
            for (int p = 0; p < 4; p++) {
                uint32_t bq[4];
                ldm_x4(bq, baddr + p * 16 * RSTRIDE + ko);
#pragma unroll
                for (int mt = 0; mt < 2; mt++) {
                    mma_f16(acc[mt][2 * p],     ah[mt], bq);
                    mma_f16(acc[mt][2 * p + 1], ah[mt], bq + 2);
                }
            }
        }
    };

    load_chunk(0, 0);
    for (int kc = 0; kc < nchunks; kc++) {
        int st = kc & 1;
        if (kc + 1 < nchunks) load_chunk(kc + 1, st ^ 1);
        if (kc + 1 < nchunks) { CP_WAIT(1); } else { CP_WAIT(0); }
        __syncthreads();
        compute(st);
        __syncthreads();
    }

#pragma unroll
    for (int mt = 0; mt < 2; mt++)
#pragma unroll
        for (int nt = 0; nt < 8; nt++) {
            int r = m0 + wm * 32 + mt * 16 + g;
            int c = n0 + wn * 64 + nt * 8 + tg * 2;
            float2 v0 = make_float2(acc[mt][nt][0], acc[mt][nt][1]);
            float2 v1 = make_float2(acc[mt][nt][2], acc[mt][nt][3]);
            *(float2*)&C[(size_t)r * N + c]       = v0;
            *(float2*)&C[(size_t)(r + 8) * N + c] = v1;
        }
}

// ---------------- mma.sync fp16 causal flash attention, 1 CTA/SM ------------
#define FQSTR 272
#define FKSTR 272
#define FVSTR 144
#define QBYTES (128 * FQSTR)
#define KSTAGE (64 * FKSTR)
#define VSTAGE (128 * FVSTR)
#define OFF_Q  0
#define OFF_K  QBYTES
#define OFF_V  (OFF_K + 2 * KSTAGE)
#define FLASH_SMEM (OFF_V + 2 * VSTAGE)      // 106496

__global__ __launch_bounds__(256, 1) void flash_mma(
    const __half* __restrict__ Qh, const __half* __restrict__ Kh,
    const __half* __restrict__ Vth, __half* __restrict__ Oh)
{
    extern __shared__ char sm[];
    const uint32_t smb = s2u(sm);
    const int tid = threadIdx.x, wid = tid >> 5, lane = tid & 31;
    const int g = lane >> 2, tg = lane & 3;
    const int lm = lane >> 3, lr = lane & 7;
    const int qb = gridDim.x - 1 - blockIdx.x;
    const int bh = blockIdx.y;
    const int b = bh / H_, h = bh % H_;
    const int kvh = h / (H_ / HKV_);
    const int q0 = qb * 128;
    const int nkb = 2 * qb + 2;

    const __half* Qhg = Qh + (((size_t)b * H_ + h) * S_ + q0) * HD_;
    const __half* Khg = Kh + ((size_t)b * HKV_ + kvh) * S_ * HD_;
    const __half* Vhg = Vth + ((size_t)b * HKV_ + kvh) * (size_t)HD_ * S_;

    for (int i = tid; i < 2048; i += 256) {
        int r = i >> 4, c = i & 15;
        cpasync16(smb + OFF_Q + r * FQSTR + c * 16, Qhg + (size_t)r * HD_ + c * 8);
    }
    CP_COMMIT();

    auto load_kv = [&](int kb, int st) {
        uint32_t kbase = smb + OFF_K + st * KSTAGE;
        const __half* kh = Khg + (size_t)kb * 64 * HD_;
        for (int i = tid; i < 1024; i += 256) {
            int r = i >> 4, c = i & 15;
            cpasync16(kbase + r * FKSTR + c * 16, kh + (size_t)r * HD_ + c * 8);
        }
        uint32_t vbase = smb + OFF_V + st * VSTAGE;
        const __half* vh = Vhg + kb * 64;
        for (int i = tid; i < 1024; i += 256) {
            int r = i >> 3, c = i & 7;
            cpasync16(vbase + r * FVSTR + c * 16, vh + (size_t)r * S_ + c * 8);
        }
        CP_COMMIT();
    };

    load_kv(0, 0);
    if (nkb > 1) load_kv(1, 1);

    float m0 = -1e30f, m1 = -1e30f, l0 = 0.f, l1 = 0.f;
    float acc[16][4];
#pragma unroll
    for (int i = 0; i < 16; i++)
#pragma unroll
        for (int j = 0; j < 4; j++) acc[i][j] = 0.f;

    const int qi0 = q0 + wid * 16 + g;
    const int qi1 = qi0 + 8;
    const int qimax = q0 + wid * 16 + 15;
    const float sc = 0.08838834764831845f;

    const uint32_t aaddr = smb + OFF_Q + (wid * 16 + (lm & 1) * 8 + lr) * FQSTR + (lm >> 1) * 16;
    const uint32_t brow_off = ((lm >> 1) * 8 + lr);
    const uint32_t bcol_off = (lm & 1) * 16;

    for (int kb = 0; kb < nkb; kb++) {
        int st = kb & 1;
        if (kb + 1 < nkb) { CP_WAIT(1); } else { CP_WAIT(0); }
        __syncthreads();

        if (kb * 64 <= qimax) {
            float c[8][4];
#pragma unroll
            for (int i = 0; i < 8; i++)
#pragma unroll
                for (int j = 0; j < 4; j++) c[i][j] = 0.f;

            uint32_t kaddr = smb + OFF_K + st * KSTAGE + brow_off * FKSTR + bcol_off;
#pragma unroll
            for (int ks = 0; ks < 8; ks++) {
                int ko = ks * 32;
                uint32_t ah[4];
                ldm_x4(ah, aaddr + ko);
#pragma unroll
                for (int p = 0; p < 4; p++) {
                    uint32_t bq[4];
                    ldm_x4(bq, kaddr + p * 16 * FKSTR + ko);
                    mma_f16(c[2 * p],     ah, bq);
                    mma_f16(c[2 * p + 1], ah, bq + 2);
                }
            }

#pragma unroll
            for (int nt = 0; nt < 8; nt++) {
                int k0c = kb * 64 + nt * 8 + tg * 2;
                c[nt][0] = (k0c     <= qi0) ? c[nt][0] * sc : -1e30f;
                c[nt][1] = (k0c + 1 <= qi0) ? c[nt][1] * sc : -1e30f;
                c[nt][2] = (k0c     <= qi1) ? c[nt][2] * sc : -1e30f;
                c[nt][3] = (k0c + 1 <= qi1) ? c[nt][3] * sc : -1e30f;
            }

            float rm0 = -1e30f, rm1 = -1e30f;
#pragma unroll
            for (int nt = 0; nt < 8; nt++) {
                rm0 = fmaxf(rm0, fmaxf(c[nt][0], c[nt][1]));
                rm1 = fmaxf(rm1, fmaxf(c[nt][2], c[nt][3]));
            }
            rm0 = fmaxf(rm0, __shfl_xor_sync(0xffffffffu, rm0, 1));
            rm0 = fmaxf(rm0, __shfl_xor_sync(0xffffffffu, rm0, 2));
            rm1 = fmaxf(rm1, __shfl_xor_sync(0xffffffffu, rm1, 1));
            rm1 = fmaxf(rm1, __shfl_xor_sync(0xffffffffu, rm1, 2));
            float mn0 = fmaxf(m0, rm0), mn1 = fmaxf(m1, rm1);
            float cr0 = __expf(m0 - mn0), cr1 = __expf(m1 - mn1);
            m0 = mn0; m1 = mn1;
            float rs0 = 0.f, rs1 = 0.f;
#pragma unroll
            for (int nt = 0; nt < 8; nt++) {
                c[nt][0] = __expf(c[nt][0] - mn0);
                c[nt][1] = __expf(c[nt][1] - mn0);
                c[nt][2] = __expf(c[nt][2] - mn1);
                c[nt][3] = __expf(c[nt][3] - mn1);
                rs0 += c[nt][0] + c[nt][1];
                rs1 += c[nt][2] + c[nt][3];
            }
            rs0 += __shfl_xor_sync(0xffffffffu, rs0, 1);
            rs0 += __shfl_xor_sync(0xffffffffu, rs0, 2);
            rs1 += __shfl_xor_sync(0xffffffffu, rs1, 1);
            rs1 += __shfl_xor_sync(0xffffffffu, rs1, 2);
            l0 = l0 * cr0 + rs0;
            l1 = l1 * cr1 + rs1;
#pragma unroll
            for (int nt = 0; nt < 16; nt++) {
                acc[nt][0] *= cr0; acc[nt][1] *= cr0;
                acc[nt][2] *= cr1; acc[nt][3] *= cr1;
            }

            uint32_t ph[4][4];
#pragma unroll
            for (int s = 0; s < 4; s++) {
                ph[s][0] = packh_hi(c[2*s][0],   c[2*s][1]);
                ph[s][1] = packh_hi(c[2*s][2],   c[2*s][3]);
                ph[s][2] = packh_hi(c[2*s+1][0], c[2*s+1][1]);
                ph[s][3] = packh_hi(c[2*s+1][2], c[2*s+1][3]);
            }

            uint32_t vaddr = smb + OFF_V + st * VSTAGE + brow_off * FVSTR + bcol_off;
#pragma unroll
            for (int s = 0; s < 4; s++) {
#pragma unroll
                for (int p = 0; p < 8; p++) {
                    uint32_t bq[4];
                    ldm_x4(bq, vaddr + p * 16 * FVSTR + s * 32);
                    mma_f16(acc[2 * p],     ph[s], bq);
                    mma_f16(acc[2 * p + 1], ph[s], bq + 2);
                }
            }
        }

        __syncthreads();
        if (kb + 2 < nkb) load_kv(kb + 2, st);
    }

    float rl0 = 1.f / l0, rl1 = 1.f / l1;
    int t0 = b * S_ + q0 + wid * 16 + g;
    size_t o0 = (size_t)t0 * (H_ * HD_) + h * HD_;
    size_t o1 = (size_t)(t0 + 8) * (H_ * HD_) + h * HD_;
#pragma unroll
    for (int nt = 0; nt < 16; nt++) {
        int d = nt * 8 + tg * 2;
        *(uint32_t*)(Oh + o0 + d) = packh_hi(acc[nt][0] * rl0, acc[nt][1] * rl0);
        *(uint32_t*)(Oh + o1 + d) = packh_hi(acc[nt][2] * rl1, acc[nt][3] * rl1);
    }
}

// ---------------------------------------------------------------------------
extern "C" void kernel_launch(void* const* d_in, const int* in_sizes, int n_in,
                              void* d_out, int out_size)
{
    const float* hidden = (const float*)d_in[0];
    const float* wq     = (const float*)d_in[1];
    const float* wk     = (const float*)d_in[2];
    const float* wv     = (const float*)d_in[3];
    const float* wo     = (const float*)d_in[4];
    const float* qw     = (const float*)d_in[5];
    const float* kw     = (const float*)d_in[6];
    const int*   pos    = (const int*)d_in[7];
    float* out = (float*)d_out;

    __half *hid16, *wqkvT, *woT, *at16, *qh, *kh, *vth;
    float4* rope;
    cudaGetSymbolAddress((void**)&hid16, g_hid);
    cudaGetSymbolAddress((void**)&wqkvT, g_wqkvT);
    cudaGetSymbolAddress((void**)&woT,   g_woT);
    cudaGetSymbolAddress((void**)&at16,  g_at);
    cudaGetSymbolAddress((void**)&qh,    g_qh);
    cudaGetSymbolAddress((void**)&kh,    g_kh);
    cudaGetSymbolAddress((void**)&vth,   g_vth);
    cudaGetSymbolAddress((void**)&rope,  g_rope);

    cudaFuncSetAttribute(gemm_qkv_fused, cudaFuncAttributeMaxDynamicSharedMemorySize,
                         (int)G_SMEM);
    cudaFuncSetAttribute(gemm_mma, cudaFuncAttributeMaxDynamicSharedMemorySize,
                         (int)G_SMEM);
    cudaFuncSetAttribute(flash_mma, cudaFuncAttributeMaxDynamicSharedMemorySize,
                         (int)FLASH_SMEM);

    // one prep launch: convert + 4 weight transposes + rope table
    prep_kernel<<<20480, 256>>>((const float4*)hidden, (uint2*)hid16,
                                wq, wk, wv, wo, wqkvT, woT, rope);

    // fused QKV projection + RMSNorm + RoPE + head transpose
    gemm_qkv_fused<<<dim3(NQKV/128, NT/128), 256, G_SMEM>>>(
        hid16, wqkvT, qw, kw, pos, rope, qh, kh, vth);

    // tensor-core causal flash attention (fp16) -> attn fp16
    flash_mma<<<dim3(S_/128, B_*H_), 256, FLASH_SMEM>>>(qh, kh, vth, at16);

    // output projection (fp16)
    gemm_mma<<<dim3(D_/128, NT/128), 256, G_SMEM>>>(at16, woT, out, NT, D_, D_);
}